// round 12
// baseline (speedup 1.0000x reference)
#include <cuda_runtime.h>
#include <cuda_bf16.h>

#define BB 16
#define CC 512
#define MM 256
#define HWN 4096
#define ATTN 32

// ---------------- scratch ----------------
__device__ float g_Y[BB*CC];
__device__ float g_S[BB];
__device__ float g_Gmax[BB*MM];
__device__ float g_ctx[BB*MM];
__device__ float g_up[BB*CC];
__device__ float g_v[BB*CC];
__device__ float g_c0[BB];
__device__ float g_P[BB*CC];
__device__ float g_Q[BB*CC];
__device__ float g_Esum[BB];
__device__ int   g_cnt[BB];

__device__ __forceinline__ void atomicMaxF(float* addr, float v) {
    int old = __float_as_int(*addr);
    while (__int_as_float(old) < v) {
        int prev = atomicCAS((int*)addr, old, __float_as_int(v));
        if (prev == old) break;
        old = prev;
    }
}

__device__ __forceinline__ float blockSum256(float v, float* red) {
    int t = threadIdx.x, lane = t & 31, warp = t >> 5;
    __syncthreads();
#pragma unroll
    for (int o = 16; o; o >>= 1) v += __shfl_xor_sync(~0u, v, o);
    if (lane == 0) red[warp] = v;
    __syncthreads();
    if (warp == 0) {
        float s = (lane < 8) ? red[lane] : 0.f;
#pragma unroll
        for (int o = 4; o; o >>= 1) s += __shfl_xor_sync(~0u, s, o);
        if (lane == 0) red[0] = s;
    }
    __syncthreads();
    return red[0];
}
__device__ __forceinline__ float blockMax256(float v, float* red) {
    int t = threadIdx.x, lane = t & 31, warp = t >> 5;
    __syncthreads();
#pragma unroll
    for (int o = 16; o; o >>= 1) v = fmaxf(v, __shfl_xor_sync(~0u, v, o));
    if (lane == 0) red[warp] = v;
    __syncthreads();
    if (warp == 0) {
        float s = (lane < 8) ? red[lane] : __int_as_float(0xff800000u);
#pragma unroll
        for (int o = 4; o; o >>= 1) s = fmaxf(s, __shfl_xor_sync(~0u, s, o));
        if (lane == 0) red[0] = s;
    }
    __syncthreads();
    return red[0];
}

// ---------------- K0: init ----------------
__global__ void k0_init() {
    int i = blockIdx.x * 256 + threadIdx.x;
    if (i < BB*CC) g_Y[i] = 0.f;
    if (i < BB*MM) g_Gmax[i] = __int_as_float(0xff800000u);
    if (i < BB) { g_S[i] = 0.f; g_Esum[i] = 0.f; g_cnt[i] = 0; }
}

// ---------------- K12: tile-teamed k1 (mask/Y) + k2 (tensor gmax) ----------------
// 1536 blocks, 256 threads, 2 CTAs/SM. Trio j = bid/3 owns tile (b = j>>5, nt = j&31):
//   bid%3==0 -> k1 role on pixels [nt*128, nt*128+128)
//   bid%3==1 -> k2 role mt=0 (weight rows 0..127)   on same pixel tile
//   bid%3==2 -> k2 role mt=1 (weight rows 128..255) on same pixel tile
// Adjacent bids land in the same wave -> the 256KB x tile is read from DRAM once
// and served from L2 for the other two roles.
#define TOTAL_BLOCKS (BB*96)
__global__ __launch_bounds__(256, 2) void k12(const float* __restrict__ x,
                                              const float* __restrict__ w_qr,
                                              const float* __restrict__ b_qr,
                                              const float* __restrict__ w_ql) {
    __shared__ __align__(16) char smem_raw[2 * 128 * 40 * 2];  // 20.5KB
    int bid = blockIdx.x, t = threadIdx.x;
    int j = bid / 3, role = bid % 3;
    int b = j >> 5, nt = j & 31;

    if (role == 0) {
        // ===== k1 role: 128 pixels, 2 threads per pixel (channel halves) =====
        float* sw    = (float*)smem_raw;         // [512]
        float* spart = sw + CC;                  // [256]
        float* se    = spart + 256;              // [128]
        for (int i = t; i < CC; i += 256) sw[i] = w_qr[i];
        __syncthreads();

        int p = t & 127, half = t >> 7;
        int h0 = nt * 128;
        int h = h0 + p;
        int c0 = half * 256;
        const float* xb = x + (size_t)b * CC * HWN;
        const float* xp = xb + (size_t)c0 * HWN + h;
        float l0=0.f,l1=0.f,l2=0.f,l3=0.f,l4=0.f,l5=0.f,l6=0.f,l7=0.f;
#pragma unroll 4
        for (int c = 0; c < 256; c += 8) {
            l0 += sw[c0+c]   * xp[(size_t)c * HWN];
            l1 += sw[c0+c+1] * xp[(size_t)(c+1) * HWN];
            l2 += sw[c0+c+2] * xp[(size_t)(c+2) * HWN];
            l3 += sw[c0+c+3] * xp[(size_t)(c+3) * HWN];
            l4 += sw[c0+c+4] * xp[(size_t)(c+4) * HWN];
            l5 += sw[c0+c+5] * xp[(size_t)(c+5) * HWN];
            l6 += sw[c0+c+6] * xp[(size_t)(c+6) * HWN];
            l7 += sw[c0+c+7] * xp[(size_t)(c+7) * HWN];
        }
        spart[t] = ((l0+l1)+(l2+l3)) + ((l4+l5)+(l6+l7));
        __syncthreads();
        if (t < 128) {
            float e = expf(b_qr[0] + spart[t] + spart[t + 128]);
            se[t] = e;
            float s = e;
#pragma unroll
            for (int o = 16; o; o >>= 1) s += __shfl_xor_sync(~0u, s, o);
            if ((t & 31) == 0) atomicAdd(&g_S[b], s);
        }
        __syncthreads();

        // Y[c] += sum over 128 pixels; 2 rows per thread (L2-hot second pass)
        const float4* se4 = (const float4*)se;
#pragma unroll
        for (int i = 0; i < 2; i++) {
            int cc = t + i * 256;
            const float4* xr = (const float4*)(xb + (size_t)cc * HWN + h0);
            float a0 = 0.f, a1 = 0.f;
#pragma unroll 8
            for (int jj = 0; jj < 32; jj += 2) {
                float4 xv = xr[jj];     float4 ev = se4[jj];
                a0 += ev.x*xv.x + ev.y*xv.y + ev.z*xv.z + ev.w*xv.w;
                float4 xw = xr[jj + 1]; float4 ew = se4[jj + 1];
                a1 += ew.x*xw.x + ew.y*xw.y + ew.z*xw.z + ew.w*xw.w;
            }
            atomicAdd(&g_Y[b*CC + cc], a0 + a1);
        }
    } else {
        // ===== k2 role: 128(M) x 128(N) tile, K=512, bf16 mma =====
        __nv_bfloat16 (*As)[40] = (__nv_bfloat16(*)[40])smem_raw;
        __nv_bfloat16 (*Bs)[40] = (__nv_bfloat16(*)[40])(smem_raw + 128 * 40 * 2);
        int mt = role - 1;
        int warp = t >> 5, lane = t & 31;
        int wm = warp >> 2, wn = warp & 3;          // 2 x 4 warps; warp tile 64x32
        const float* xb = x + (size_t)b * CC * HWN + nt * 128;
        const float* wq = w_ql + (size_t)mt * 128 * CC;

        float acc[4][4][4];
#pragma unroll
        for (int i = 0; i < 4; i++)
#pragma unroll
            for (int jj = 0; jj < 4; jj++)
#pragma unroll
                for (int k = 0; k < 4; k++) acc[i][jj][k] = 0.f;

        // prologue: stage B slice 0
        float bstage[16];
#pragma unroll
        for (int p = 0; p < 16; p++) {
            int i = t + p * 256;
            int n = i & 127, k = i >> 7;
            bstage[p] = xb[(size_t)k * HWN + n];
        }

        for (int k0 = 0; k0 < CC; k0 += 32) {
            __syncthreads();
#pragma unroll
            for (int p = 0; p < 16; p++) {          // staged B -> smem
                int i = t + p * 256;
                int n = i & 127, k = i >> 7;
                Bs[n][k] = __float2bfloat16(bstage[p]);
            }
#pragma unroll
            for (int p = 0; p < 16; p++) {          // A direct (L2-resident weights)
                int i = t + p * 256;
                int m = i >> 5, k = i & 31;
                As[m][k] = __float2bfloat16(wq[m * CC + k0 + k]);
            }
            __syncthreads();
            if (k0 + 32 < CC) {                     // prefetch next B slice
#pragma unroll
                for (int p = 0; p < 16; p++) {
                    int i = t + p * 256;
                    int n = i & 127, k = i >> 7;
                    bstage[p] = xb[(size_t)(k0 + 32 + k) * HWN + n];
                }
            }
#pragma unroll
            for (int kb = 0; kb < 32; kb += 16) {
                unsigned af[4][4], bf[4][2];
                int cq = kb + (lane & 3) * 2;
#pragma unroll
                for (int mf = 0; mf < 4; mf++) {
                    int r = wm * 64 + mf * 16 + (lane >> 2);
                    af[mf][0] = *(const unsigned*)&As[r][cq];
                    af[mf][1] = *(const unsigned*)&As[r + 8][cq];
                    af[mf][2] = *(const unsigned*)&As[r][cq + 8];
                    af[mf][3] = *(const unsigned*)&As[r + 8][cq + 8];
                }
#pragma unroll
                for (int nf = 0; nf < 4; nf++) {
                    int n = wn * 32 + nf * 8 + (lane >> 2);
                    bf[nf][0] = *(const unsigned*)&Bs[n][cq];
                    bf[nf][1] = *(const unsigned*)&Bs[n][cq + 8];
                }
#pragma unroll
                for (int mf = 0; mf < 4; mf++)
#pragma unroll
                    for (int nf = 0; nf < 4; nf++)
                        asm volatile(
                            "mma.sync.aligned.m16n8k16.row.col.f32.bf16.bf16.f32 "
                            "{%0,%1,%2,%3}, {%4,%5,%6,%7}, {%8,%9}, {%0,%1,%2,%3};\n"
                            : "+f"(acc[mf][nf][0]), "+f"(acc[mf][nf][1]),
                              "+f"(acc[mf][nf][2]), "+f"(acc[mf][nf][3])
                            : "r"(af[mf][0]), "r"(af[mf][1]), "r"(af[mf][2]), "r"(af[mf][3]),
                              "r"(bf[nf][0]), "r"(bf[nf][1]));
            }
        }
#pragma unroll
        for (int mf = 0; mf < 4; mf++) {
            float m0 = __int_as_float(0xff800000u), m1 = m0;
#pragma unroll
            for (int nf = 0; nf < 4; nf++) {
                m0 = fmaxf(m0, fmaxf(acc[mf][nf][0], acc[mf][nf][1]));
                m1 = fmaxf(m1, fmaxf(acc[mf][nf][2], acc[mf][nf][3]));
            }
            m0 = fmaxf(m0, __shfl_xor_sync(~0u, m0, 1));
            m0 = fmaxf(m0, __shfl_xor_sync(~0u, m0, 2));
            m1 = fmaxf(m1, __shfl_xor_sync(~0u, m1, 1));
            m1 = fmaxf(m1, __shfl_xor_sync(~0u, m1, 2));
            if ((lane & 3) == 0) {
                int r = mt * 128 + wm * 64 + mf * 16 + (lane >> 2);
                atomicMaxF(&g_Gmax[b * MM + r], m0);
                atomicMaxF(&g_Gmax[b * MM + r + 8], m1);
            }
        }
    }
}

// ---------------- K3av: blk 0..7 -> context rows; blk 8 -> softmax/v/c0.  grid (B,9) ----------------
__global__ void k3av(const float* __restrict__ w_vr, const float* __restrict__ b_vr,
                     const float* __restrict__ b_ql,
                     const float* __restrict__ w_vl, const float* __restrict__ b_vl) {
    int b = blockIdx.x, blk = blockIdx.y, t = threadIdx.x;
    int warp = t >> 5, lane = t & 31;
    if (blk < 8) {
        __shared__ float sy[CC];
        float Sinv = 1.f / g_S[b];
        for (int i = t; i < CC; i += 256) sy[i] = g_Y[b*CC + i] * Sinv;
        __syncthreads();
#pragma unroll
        for (int i = 0; i < 4; i++) {
            int r = blk * 32 + warp * 4 + i;
            const float* wr = w_vr + (size_t)r * CC;
            float a = 0.f;
#pragma unroll
            for (int c = lane; c < CC; c += 32) a += wr[c] * sy[c];
#pragma unroll
            for (int o = 16; o; o >>= 1) a += __shfl_xor_sync(~0u, a, o);
            if (lane == 0) g_ctx[b*MM + r] = a + b_vr[r];
        }
    } else {
        __shared__ float savg[MM];
        __shared__ float red[8];
        float gv = g_Gmax[b*MM + t] + b_ql[t];
        float gm = blockMax256(gv, red);
        float ge = expf(gv - gm);
        float gs = blockSum256(ge, red);
        savg[t] = ge / gs;
        float c0 = blockSum256((ge / gs) * b_vl[t], red);
        if (t == 0) g_c0[b] = c0;
        __syncthreads();
        float a0 = 0.f, a1 = 0.f;
#pragma unroll 8
        for (int m = 0; m < MM; m++) {
            float av = savg[m];
            const float* wr = w_vl + (size_t)m * CC;
            a0 += av * wr[t];
            a1 += av * wr[t + 256];
        }
        g_v[b*CC + t]       = a0;
        g_v[b*CC + t + 256] = a1;
    }
}

// ---------------- K3b: up = W_up @ ctx + b_up.  grid (B, 16) ----------------
__global__ void k3b(const float* __restrict__ w_up, const float* __restrict__ b_up) {
    __shared__ float sc[MM];
    int b = blockIdx.x, blk = blockIdx.y, t = threadIdx.x;
    int warp = t >> 5, lane = t & 31;
    if (t < MM) sc[t] = g_ctx[b*MM + t];
    __syncthreads();
#pragma unroll
    for (int i = 0; i < 4; i++) {
        int r = blk * 32 + warp * 4 + i;
        const float* wr = w_up + (size_t)r * MM;
        float a = 0.f;
#pragma unroll
        for (int m = lane; m < MM; m += 32) a += wr[m] * sc[m];
#pragma unroll
        for (int o = 16; o; o >>= 1) a += __shfl_xor_sync(~0u, a, o);
        if (lane == 0) g_up[b*CC + r] = a + b_up[r];
    }
}

// ---------------- K3c: LN + sigmoid + SK-attn -> P,Q.  grid B ----------------
__global__ void k3c(const float* __restrict__ ln_g, const float* __restrict__ ln_b,
                    const float* __restrict__ w_red, const float* __restrict__ bn_g,
                    const float* __restrict__ bn_b, const float* __restrict__ bn_rm,
                    const float* __restrict__ bn_rv, const float* __restrict__ w_sel) {
    __shared__ float sy[CC];
    __shared__ float sca[CC];
    __shared__ float ssk[ATTN];
    __shared__ float red[8];
    int b = blockIdx.x, t = threadIdx.x;
    int warp = t >> 5, lane = t & 31;

    float u0 = g_up[b*CC + t], u1 = g_up[b*CC + t + 256];
    float mean = blockSum256(u0 + u1, red) * (1.f / CC);
    float var  = blockSum256(u0*u0 + u1*u1, red) * (1.f / CC) - mean * mean;
    float rstd = rsqrtf(var + 1e-5f);
    sca[t]       = 1.f / (1.f + expf(-((u0 - mean) * rstd * ln_g[t] + ln_b[t])));
    sca[t + 256] = 1.f / (1.f + expf(-((u1 - mean) * rstd * ln_g[t + 256] + ln_b[t + 256])));

    const float invHW = 1.f / (float)HWN;
    sy[t]       = sca[t]       * (1.f + invHW) + invHW;
    sy[t + 256] = sca[t + 256] * (1.f + invHW) + invHW;
    __syncthreads();

#pragma unroll
    for (int i = 0; i < 4; i++) {
        int r = warp * 4 + i;
        const float* wr = w_red + (size_t)r * CC;
        float a = 0.f;
#pragma unroll
        for (int c = lane; c < CC; c += 32) a += wr[c] * sy[c];
#pragma unroll
        for (int o = 16; o; o >>= 1) a += __shfl_xor_sync(~0u, a, o);
        if (lane == 0) {
            a = (a - bn_rm[r]) * rsqrtf(bn_rv[r] + 1e-5f) * bn_g[r] + bn_b[r];
            ssk[r] = fmaxf(a, 0.f);
        }
    }
    __syncthreads();

#pragma unroll
    for (int i = 0; i < 2; i++) {
        int c = t + i * 256;
        float s0 = 0.f, s1 = 0.f;
        const float* w0 = w_sel + (size_t)c * ATTN;
        const float* w1 = w_sel + (size_t)(CC + c) * ATTN;
#pragma unroll
        for (int a = 0; a < ATTN; a++) { s0 += w0[a] * ssk[a]; s1 += w1[a] * ssk[a]; }
        float mx = fmaxf(s0, s1);
        float e0 = expf(s0 - mx), e1 = expf(s1 - mx);
        float inv = 1.f / (e0 + e1);
        float a0 = e0 * inv, a1 = e1 * inv;
        float ca = sca[c];
        g_P[b*CC + c] = a0 * ca + a1;
        g_Q[b*CC + c] = a1 * ca;
    }
}

// ---------------- K45: fused ctx+exp+Esum (per-batch spin barrier) + final output ----
__global__ __launch_bounds__(256) void k45(const float* __restrict__ x,
                                           float* __restrict__ out) {
    __shared__ float sv[CC];
    __shared__ float sP[CC];
    __shared__ float sQ[CC];
    __shared__ float spart[256];
    __shared__ float se[128];
    __shared__ float red[4];
    __shared__ float sEinv;
    int b = blockIdx.x, chunk = blockIdx.y, t = threadIdx.x;
    for (int i = t; i < CC; i += 256) {
        sv[i] = g_v[b*CC + i];
        sP[i] = g_P[b*CC + i];
        sQ[i] = g_Q[b*CC + i];
    }
    __syncthreads();

    int p = t & 127, half = t >> 7;
    int c0 = half * 256;
    int h0 = chunk * 128;
    const float* xb = x + (size_t)b * CC * HWN;
    const float* xp = xb + (size_t)c0 * HWN + h0 + p;
    float a0 = 0.f, a1 = 0.f, a2 = 0.f, a3 = 0.f;
#pragma unroll 8
    for (int c = 0; c < 256; c += 4) {
        a0 += sv[c0 + c]     * xp[(size_t)c * HWN];
        a1 += sv[c0 + c + 1] * xp[(size_t)(c + 1) * HWN];
        a2 += sv[c0 + c + 2] * xp[(size_t)(c + 2) * HWN];
        a3 += sv[c0 + c + 3] * xp[(size_t)(c + 3) * HWN];
    }
    spart[t] = (a0 + a1) + (a2 + a3);
    __syncthreads();
    if (t < 128) {
        float e = expf(g_c0[b] + spart[t] + spart[t + 128]);
        se[t] = e;
        float s = e;
#pragma unroll
        for (int o = 16; o; o >>= 1) s += __shfl_xor_sync(~0u, s, o);
        if ((t & 31) == 0) red[t >> 5] = s;
    }
    __syncthreads();
    if (t == 0) {
        atomicAdd(&g_Esum[b], (red[0] + red[1]) + (red[2] + red[3]));
        __threadfence();
        atomicAdd(&g_cnt[b], 1);
        volatile int* vc = (volatile int*)&g_cnt[b];
        while (*vc < 32) { }
        __threadfence();
        sEinv = 1.f / *((volatile float*)&g_Esum[b]);
    }
    __syncthreads();
    float inv = sEinv;

    const float4* se4 = (const float4*)se;
    const float4* x4 = (const float4*)(xb + h0);
    float4* o4 = (float4*)(out + (size_t)b * CC * HWN + h0);
    for (int i = t; i < CC * 32; i += 256) {
        int row = i >> 5, f4 = i & 31;
        float4 xv = x4[(size_t)row * (HWN/4) + f4];
        float4 ev = se4[f4];
        float P = sP[row], base = 1.f + sQ[row];
        float4 o;
        o.x = xv.x * (base + P * ev.x * inv);
        o.y = xv.y * (base + P * ev.y * inv);
        o.z = xv.z * (base + P * ev.z * inv);
        o.w = xv.w * (base + P * ev.w * inv);
        o4[(size_t)row * (HWN/4) + f4] = o;
    }
}

// ---------------- launch ----------------
extern "C" void kernel_launch(void* const* d_in, const int* in_sizes, int n_in,
                              void* d_out, int out_size) {
    const float* x     = (const float*)d_in[0];
    const float* w_qr  = (const float*)d_in[1];
    const float* b_qr  = (const float*)d_in[2];
    const float* w_vr  = (const float*)d_in[3];
    const float* b_vr  = (const float*)d_in[4];
    const float* w_up  = (const float*)d_in[5];
    const float* b_up  = (const float*)d_in[6];
    const float* ln_g  = (const float*)d_in[7];
    const float* ln_b  = (const float*)d_in[8];
    const float* w_ql  = (const float*)d_in[9];
    const float* b_ql  = (const float*)d_in[10];
    const float* w_vl  = (const float*)d_in[11];
    const float* b_vl  = (const float*)d_in[12];
    const float* w_red = (const float*)d_in[13];
    const float* bn_g  = (const float*)d_in[14];
    const float* bn_b  = (const float*)d_in[15];
    const float* bn_rm = (const float*)d_in[16];
    const float* bn_rv = (const float*)d_in[17];
    const float* w_sel = (const float*)d_in[18];
    float* out = (float*)d_out;

    k0_init<<<32, 256>>>();
    k12<<<TOTAL_BLOCKS, 256>>>(x, w_qr, b_qr, w_ql);
    k3av<<<dim3(BB, 9), 256>>>(w_vr, b_vr, b_ql, w_vl, b_vl);
    k3b<<<dim3(BB, 16), 256>>>(w_up, b_up);
    k3c<<<BB, 256>>>(ln_g, ln_b, w_red, bn_g, bn_b, bn_rm, bn_rv, w_sel);
    k45<<<dim3(BB, 32), 256>>>(x, out);
}

// round 13
// speedup vs baseline: 1.0345x; 1.0345x over previous
#include <cuda_runtime.h>
#include <cuda_bf16.h>

#define BB 16
#define CC 512
#define MM 256
#define HWN 4096
#define ATTN 32

// ---------------- scratch ----------------
__device__ float g_Y[BB*CC];
__device__ float g_S[BB];
__device__ float g_Gmax[BB*MM];
__device__ float g_ctx[BB*MM];
__device__ float g_up[BB*CC];
__device__ float g_v[BB*CC];
__device__ float g_c0[BB];
__device__ float g_P[BB*CC];
__device__ float g_Q[BB*CC];
__device__ float g_Esum[BB];
__device__ int   g_cnt[BB];

__device__ __forceinline__ void atomicMaxF(float* addr, float v) {
    int old = __float_as_int(*addr);
    while (__int_as_float(old) < v) {
        int prev = atomicCAS((int*)addr, old, __float_as_int(v));
        if (prev == old) break;
        old = prev;
    }
}

__device__ __forceinline__ float blockSum256(float v, float* red) {
    int t = threadIdx.x, lane = t & 31, warp = t >> 5;
    __syncthreads();
#pragma unroll
    for (int o = 16; o; o >>= 1) v += __shfl_xor_sync(~0u, v, o);
    if (lane == 0) red[warp] = v;
    __syncthreads();
    if (warp == 0) {
        float s = (lane < 8) ? red[lane] : 0.f;
#pragma unroll
        for (int o = 4; o; o >>= 1) s += __shfl_xor_sync(~0u, s, o);
        if (lane == 0) red[0] = s;
    }
    __syncthreads();
    return red[0];
}
__device__ __forceinline__ float blockMax256(float v, float* red) {
    int t = threadIdx.x, lane = t & 31, warp = t >> 5;
    __syncthreads();
#pragma unroll
    for (int o = 16; o; o >>= 1) v = fmaxf(v, __shfl_xor_sync(~0u, v, o));
    if (lane == 0) red[warp] = v;
    __syncthreads();
    if (warp == 0) {
        float s = (lane < 8) ? red[lane] : __int_as_float(0xff800000u);
#pragma unroll
        for (int o = 4; o; o >>= 1) s = fmaxf(s, __shfl_xor_sync(~0u, s, o));
        if (lane == 0) red[0] = s;
    }
    __syncthreads();
    return red[0];
}

// ---------------- K0 split into 3 (so k12 is the 4th launch -> gets profiled) ----------------
__global__ void k0a_init() {                 // Y
    int i = blockIdx.x * 256 + threadIdx.x;
    if (i < BB*CC) g_Y[i] = 0.f;
}
__global__ void k0b_init() {                 // Gmax
    int i = blockIdx.x * 256 + threadIdx.x;
    if (i < BB*MM) g_Gmax[i] = __int_as_float(0xff800000u);
}
__global__ void k0c_init() {                 // small scalars
    int i = threadIdx.x;
    if (i < BB) { g_S[i] = 0.f; g_Esum[i] = 0.f; g_cnt[i] = 0; }
}

// ---------------- K12: interleaved k1 (mask/Y) + k2 (tensor gmax, ldmatrix) ----------------
// R9 mapping: 1536 blocks, 256 threads, 2 CTAs/SM.
// bid%3==0 -> k1 role (512: b x 32 chunks of 128 px).
// else k2 role (1024: b, mt, nt), 128x128 tile K=512, reg-staged B prefetch.
#define TOTAL_BLOCKS (BB*96)
__global__ __launch_bounds__(256, 2) void k12(const float* __restrict__ x,
                                              const float* __restrict__ w_qr,
                                              const float* __restrict__ b_qr,
                                              const float* __restrict__ w_ql) {
    __shared__ __align__(16) char smem_raw[2 * 128 * 40 * 2];  // 20.5KB
    int bid = blockIdx.x, t = threadIdx.x;

    if (bid % 3 == 0) {
        // ===== k1 role: 128 pixels, 2 threads per pixel (channel halves) =====
        int k1id = bid / 3;
        int b = k1id >> 5, chunk = k1id & 31;
        float* sw    = (float*)smem_raw;         // [512]
        float* spart = sw + CC;                  // [256]
        float* se    = spart + 256;              // [128]
        for (int i = t; i < CC; i += 256) sw[i] = w_qr[i];
        __syncthreads();

        int p = t & 127, half = t >> 7;
        int h0 = chunk * 128;
        int h = h0 + p;
        int c0 = half * 256;
        const float* xb = x + (size_t)b * CC * HWN;
        const float* xp = xb + (size_t)c0 * HWN + h;
        float l0=0.f,l1=0.f,l2=0.f,l3=0.f,l4=0.f,l5=0.f,l6=0.f,l7=0.f;
#pragma unroll 4
        for (int c = 0; c < 256; c += 8) {
            l0 += sw[c0+c]   * xp[(size_t)c * HWN];
            l1 += sw[c0+c+1] * xp[(size_t)(c+1) * HWN];
            l2 += sw[c0+c+2] * xp[(size_t)(c+2) * HWN];
            l3 += sw[c0+c+3] * xp[(size_t)(c+3) * HWN];
            l4 += sw[c0+c+4] * xp[(size_t)(c+4) * HWN];
            l5 += sw[c0+c+5] * xp[(size_t)(c+5) * HWN];
            l6 += sw[c0+c+6] * xp[(size_t)(c+6) * HWN];
            l7 += sw[c0+c+7] * xp[(size_t)(c+7) * HWN];
        }
        spart[t] = ((l0+l1)+(l2+l3)) + ((l4+l5)+(l6+l7));
        __syncthreads();
        if (t < 128) {
            float e = expf(b_qr[0] + spart[t] + spart[t + 128]);
            se[t] = e;
            float s = e;
#pragma unroll
            for (int o = 16; o; o >>= 1) s += __shfl_xor_sync(~0u, s, o);
            if ((t & 31) == 0) atomicAdd(&g_S[b], s);
        }
        __syncthreads();

        // Y[c] += sum over 128 pixels; 2 rows per thread (second pass L2-hot)
        const float4* se4 = (const float4*)se;
#pragma unroll
        for (int i = 0; i < 2; i++) {
            int cc = t + i * 256;
            const float4* xr = (const float4*)(xb + (size_t)cc * HWN + h0);
            float a0 = 0.f, a1 = 0.f;
#pragma unroll 8
            for (int j = 0; j < 32; j += 2) {
                float4 xv = xr[j];     float4 ev = se4[j];
                a0 += ev.x*xv.x + ev.y*xv.y + ev.z*xv.z + ev.w*xv.w;
                float4 xw = xr[j + 1]; float4 ew = se4[j + 1];
                a1 += ew.x*xw.x + ew.y*xw.y + ew.z*xw.z + ew.w*xw.w;
            }
            atomicAdd(&g_Y[b*CC + cc], a0 + a1);
        }
    } else {
        // ===== k2 role: 128(M) x 128(N) tile, K=512, bf16 mma + ldmatrix =====
        __nv_bfloat16 (*As)[40] = (__nv_bfloat16(*)[40])smem_raw;
        __nv_bfloat16 (*Bs)[40] = (__nv_bfloat16(*)[40])(smem_raw + 128 * 40 * 2);
        int k2id = bid - bid / 3 - 1;
        int b = k2id >> 6, r6 = k2id & 63;
        int mt = r6 >> 5, nt = r6 & 31;
        int warp = t >> 5, lane = t & 31;
        int wm = warp >> 2, wn = warp & 3;          // 2 x 4 warps; warp tile 64x32
        const float* xb = x + (size_t)b * CC * HWN + nt * 128;
        const float* wq = w_ql + (size_t)mt * 128 * CC;

        float acc[4][4][4];
#pragma unroll
        for (int i = 0; i < 4; i++)
#pragma unroll
            for (int j = 0; j < 4; j++)
#pragma unroll
                for (int k = 0; k < 4; k++) acc[i][j][k] = 0.f;

        // prologue: stage B slice 0
        float bstage[16];
#pragma unroll
        for (int p = 0; p < 16; p++) {
            int i = t + p * 256;
            int n = i & 127, k = i >> 7;
            bstage[p] = xb[(size_t)k * HWN + n];
        }

        // ldmatrix lane address components (constant across kb loop)
        int a_row = (lane & 15);            // row within 16-row fragment
        int a_c8  = (lane >> 4) << 3;       // 0 or 8 (k-halves)
        int b_row = (lane & 7);             // row within 8-row fragment
        int b_c8  = ((lane >> 3) & 1) << 3; // 0 or 8 (only lanes 0-15 used by x2)

        for (int k0 = 0; k0 < CC; k0 += 32) {
            __syncthreads();
#pragma unroll
            for (int p = 0; p < 16; p++) {          // staged B -> smem
                int i = t + p * 256;
                int n = i & 127, k = i >> 7;
                Bs[n][k] = __float2bfloat16(bstage[p]);
            }
#pragma unroll
            for (int p = 0; p < 16; p++) {          // A direct (L2-resident weights)
                int i = t + p * 256;
                int m = i >> 5, k = i & 31;
                As[m][k] = __float2bfloat16(wq[m * CC + k0 + k]);
            }
            __syncthreads();
            if (k0 + 32 < CC) {                     // prefetch next B slice
#pragma unroll
                for (int p = 0; p < 16; p++) {
                    int i = t + p * 256;
                    int n = i & 127, k = i >> 7;
                    bstage[p] = xb[(size_t)(k0 + 32 + k) * HWN + n];
                }
            }
#pragma unroll
            for (int kb = 0; kb < 32; kb += 16) {
                unsigned af[4][4], bf[4][2];
#pragma unroll
                for (int mf = 0; mf < 4; mf++) {
                    unsigned addr = (unsigned)__cvta_generic_to_shared(
                        &As[wm * 64 + mf * 16 + a_row][kb + a_c8]);
                    asm volatile(
                        "ldmatrix.sync.aligned.m8n8.x4.shared.b16 {%0,%1,%2,%3}, [%4];"
                        : "=r"(af[mf][0]), "=r"(af[mf][1]), "=r"(af[mf][2]), "=r"(af[mf][3])
                        : "r"(addr));
                }
#pragma unroll
                for (int nf = 0; nf < 4; nf++) {
                    unsigned addr = (unsigned)__cvta_generic_to_shared(
                        &Bs[wn * 32 + nf * 8 + b_row][kb + b_c8]);
                    asm volatile(
                        "ldmatrix.sync.aligned.m8n8.x2.shared.b16 {%0,%1}, [%2];"
                        : "=r"(bf[nf][0]), "=r"(bf[nf][1])
                        : "r"(addr));
                }
#pragma unroll
                for (int mf = 0; mf < 4; mf++)
#pragma unroll
                    for (int nf = 0; nf < 4; nf++)
                        asm volatile(
                            "mma.sync.aligned.m16n8k16.row.col.f32.bf16.bf16.f32 "
                            "{%0,%1,%2,%3}, {%4,%5,%6,%7}, {%8,%9}, {%0,%1,%2,%3};\n"
                            : "+f"(acc[mf][nf][0]), "+f"(acc[mf][nf][1]),
                              "+f"(acc[mf][nf][2]), "+f"(acc[mf][nf][3])
                            : "r"(af[mf][0]), "r"(af[mf][1]), "r"(af[mf][2]), "r"(af[mf][3]),
                              "r"(bf[nf][0]), "r"(bf[nf][1]));
            }
        }
#pragma unroll
        for (int mf = 0; mf < 4; mf++) {
            float m0 = __int_as_float(0xff800000u), m1 = m0;
#pragma unroll
            for (int nf = 0; nf < 4; nf++) {
                m0 = fmaxf(m0, fmaxf(acc[mf][nf][0], acc[mf][nf][1]));
                m1 = fmaxf(m1, fmaxf(acc[mf][nf][2], acc[mf][nf][3]));
            }
            m0 = fmaxf(m0, __shfl_xor_sync(~0u, m0, 1));
            m0 = fmaxf(m0, __shfl_xor_sync(~0u, m0, 2));
            m1 = fmaxf(m1, __shfl_xor_sync(~0u, m1, 1));
            m1 = fmaxf(m1, __shfl_xor_sync(~0u, m1, 2));
            if ((lane & 3) == 0) {
                int r = mt * 128 + wm * 64 + mf * 16 + (lane >> 2);
                atomicMaxF(&g_Gmax[b * MM + r], m0);
                atomicMaxF(&g_Gmax[b * MM + r + 8], m1);
            }
        }
    }
}

// ---------------- K3av: blk 0..7 -> context rows; blk 8 -> softmax/v/c0.  grid (B,9) ----------------
__global__ void k3av(const float* __restrict__ w_vr, const float* __restrict__ b_vr,
                     const float* __restrict__ b_ql,
                     const float* __restrict__ w_vl, const float* __restrict__ b_vl) {
    int b = blockIdx.x, blk = blockIdx.y, t = threadIdx.x;
    int warp = t >> 5, lane = t & 31;
    if (blk < 8) {
        __shared__ float sy[CC];
        float Sinv = 1.f / g_S[b];
        for (int i = t; i < CC; i += 256) sy[i] = g_Y[b*CC + i] * Sinv;
        __syncthreads();
#pragma unroll
        for (int i = 0; i < 4; i++) {
            int r = blk * 32 + warp * 4 + i;
            const float* wr = w_vr + (size_t)r * CC;
            float a = 0.f;
#pragma unroll
            for (int c = lane; c < CC; c += 32) a += wr[c] * sy[c];
#pragma unroll
            for (int o = 16; o; o >>= 1) a += __shfl_xor_sync(~0u, a, o);
            if (lane == 0) g_ctx[b*MM + r] = a + b_vr[r];
        }
    } else {
        __shared__ float savg[MM];
        __shared__ float red[8];
        float gv = g_Gmax[b*MM + t] + b_ql[t];
        float gm = blockMax256(gv, red);
        float ge = expf(gv - gm);
        float gs = blockSum256(ge, red);
        savg[t] = ge / gs;
        float c0 = blockSum256((ge / gs) * b_vl[t], red);
        if (t == 0) g_c0[b] = c0;
        __syncthreads();
        float a0 = 0.f, a1 = 0.f;
#pragma unroll 8
        for (int m = 0; m < MM; m++) {
            float av = savg[m];
            const float* wr = w_vl + (size_t)m * CC;
            a0 += av * wr[t];
            a1 += av * wr[t + 256];
        }
        g_v[b*CC + t]       = a0;
        g_v[b*CC + t + 256] = a1;
    }
}

// ---------------- K3b: up = W_up @ ctx + b_up.  grid (B, 16) ----------------
__global__ void k3b(const float* __restrict__ w_up, const float* __restrict__ b_up) {
    __shared__ float sc[MM];
    int b = blockIdx.x, blk = blockIdx.y, t = threadIdx.x;
    int warp = t >> 5, lane = t & 31;
    if (t < MM) sc[t] = g_ctx[b*MM + t];
    __syncthreads();
#pragma unroll
    for (int i = 0; i < 4; i++) {
        int r = blk * 32 + warp * 4 + i;
        const float* wr = w_up + (size_t)r * MM;
        float a = 0.f;
#pragma unroll
        for (int m = lane; m < MM; m += 32) a += wr[m] * sc[m];
#pragma unroll
        for (int o = 16; o; o >>= 1) a += __shfl_xor_sync(~0u, a, o);
        if (lane == 0) g_up[b*CC + r] = a + b_up[r];
    }
}

// ---------------- K3c: LN + sigmoid + SK-attn -> P,Q.  grid B ----------------
__global__ void k3c(const float* __restrict__ ln_g, const float* __restrict__ ln_b,
                    const float* __restrict__ w_red, const float* __restrict__ bn_g,
                    const float* __restrict__ bn_b, const float* __restrict__ bn_rm,
                    const float* __restrict__ bn_rv, const float* __restrict__ w_sel) {
    __shared__ float sy[CC];
    __shared__ float sca[CC];
    __shared__ float ssk[ATTN];
    __shared__ float red[8];
    int b = blockIdx.x, t = threadIdx.x;
    int warp = t >> 5, lane = t & 31;

    float u0 = g_up[b*CC + t], u1 = g_up[b*CC + t + 256];
    float mean = blockSum256(u0 + u1, red) * (1.f / CC);
    float var  = blockSum256(u0*u0 + u1*u1, red) * (1.f / CC) - mean * mean;
    float rstd = rsqrtf(var + 1e-5f);
    sca[t]       = 1.f / (1.f + expf(-((u0 - mean) * rstd * ln_g[t] + ln_b[t])));
    sca[t + 256] = 1.f / (1.f + expf(-((u1 - mean) * rstd * ln_g[t + 256] + ln_b[t + 256])));

    const float invHW = 1.f / (float)HWN;
    sy[t]       = sca[t]       * (1.f + invHW) + invHW;
    sy[t + 256] = sca[t + 256] * (1.f + invHW) + invHW;
    __syncthreads();

#pragma unroll
    for (int i = 0; i < 4; i++) {
        int r = warp * 4 + i;
        const float* wr = w_red + (size_t)r * CC;
        float a = 0.f;
#pragma unroll
        for (int c = lane; c < CC; c += 32) a += wr[c] * sy[c];
#pragma unroll
        for (int o = 16; o; o >>= 1) a += __shfl_xor_sync(~0u, a, o);
        if (lane == 0) {
            a = (a - bn_rm[r]) * rsqrtf(bn_rv[r] + 1e-5f) * bn_g[r] + bn_b[r];
            ssk[r] = fmaxf(a, 0.f);
        }
    }
    __syncthreads();

#pragma unroll
    for (int i = 0; i < 2; i++) {
        int c = t + i * 256;
        float s0 = 0.f, s1 = 0.f;
        const float* w0 = w_sel + (size_t)c * ATTN;
        const float* w1 = w_sel + (size_t)(CC + c) * ATTN;
#pragma unroll
        for (int a = 0; a < ATTN; a++) { s0 += w0[a] * ssk[a]; s1 += w1[a] * ssk[a]; }
        float mx = fmaxf(s0, s1);
        float e0 = expf(s0 - mx), e1 = expf(s1 - mx);
        float inv = 1.f / (e0 + e1);
        float a0 = e0 * inv, a1 = e1 * inv;
        float ca = sca[c];
        g_P[b*CC + c] = a0 * ca + a1;
        g_Q[b*CC + c] = a1 * ca;
    }
}

// ---------------- K45: fused ctx+exp+Esum (per-batch spin barrier) + final output ----
__global__ __launch_bounds__(256) void k45(const float* __restrict__ x,
                                           float* __restrict__ out) {
    __shared__ float sv[CC];
    __shared__ float sP[CC];
    __shared__ float sQ[CC];
    __shared__ float spart[256];
    __shared__ float se[128];
    __shared__ float red[4];
    __shared__ float sEinv;
    int b = blockIdx.x, chunk = blockIdx.y, t = threadIdx.x;
    for (int i = t; i < CC; i += 256) {
        sv[i] = g_v[b*CC + i];
        sP[i] = g_P[b*CC + i];
        sQ[i] = g_Q[b*CC + i];
    }
    __syncthreads();

    int p = t & 127, half = t >> 7;
    int c0 = half * 256;
    int h0 = chunk * 128;
    const float* xb = x + (size_t)b * CC * HWN;
    const float* xp = xb + (size_t)c0 * HWN + h0 + p;
    float a0 = 0.f, a1 = 0.f, a2 = 0.f, a3 = 0.f;
#pragma unroll 8
    for (int c = 0; c < 256; c += 4) {
        a0 += sv[c0 + c]     * xp[(size_t)c * HWN];
        a1 += sv[c0 + c + 1] * xp[(size_t)(c + 1) * HWN];
        a2 += sv[c0 + c + 2] * xp[(size_t)(c + 2) * HWN];
        a3 += sv[c0 + c + 3] * xp[(size_t)(c + 3) * HWN];
    }
    spart[t] = (a0 + a1) + (a2 + a3);
    __syncthreads();
    if (t < 128) {
        float e = expf(g_c0[b] + spart[t] + spart[t + 128]);
        se[t] = e;
        float s = e;
#pragma unroll
        for (int o = 16; o; o >>= 1) s += __shfl_xor_sync(~0u, s, o);
        if ((t & 31) == 0) red[t >> 5] = s;
    }
    __syncthreads();
    if (t == 0) {
        atomicAdd(&g_Esum[b], (red[0] + red[1]) + (red[2] + red[3]));
        __threadfence();
        atomicAdd(&g_cnt[b], 1);
        volatile int* vc = (volatile int*)&g_cnt[b];
        while (*vc < 32) { }
        __threadfence();
        sEinv = 1.f / *((volatile float*)&g_Esum[b]);
    }
    __syncthreads();
    float inv = sEinv;

    const float4* se4 = (const float4*)se;
    const float4* x4 = (const float4*)(xb + h0);
    float4* o4 = (float4*)(out + (size_t)b * CC * HWN + h0);
    for (int i = t; i < CC * 32; i += 256) {
        int row = i >> 5, f4 = i & 31;
        float4 xv = x4[(size_t)row * (HWN/4) + f4];
        float4 ev = se4[f4];
        float P = sP[row], base = 1.f + sQ[row];
        float4 o;
        o.x = xv.x * (base + P * ev.x * inv);
        o.y = xv.y * (base + P * ev.y * inv);
        o.z = xv.z * (base + P * ev.z * inv);
        o.w = xv.w * (base + P * ev.w * inv);
        o4[(size_t)row * (HWN/4) + f4] = o;
    }
}

// ---------------- launch ----------------
extern "C" void kernel_launch(void* const* d_in, const int* in_sizes, int n_in,
                              void* d_out, int out_size) {
    const float* x     = (const float*)d_in[0];
    const float* w_qr  = (const float*)d_in[1];
    const float* b_qr  = (const float*)d_in[2];
    const float* w_vr  = (const float*)d_in[3];
    const float* b_vr  = (const float*)d_in[4];
    const float* w_up  = (const float*)d_in[5];
    const float* b_up  = (const float*)d_in[6];
    const float* ln_g  = (const float*)d_in[7];
    const float* ln_b  = (const float*)d_in[8];
    const float* w_ql  = (const float*)d_in[9];
    const float* b_ql  = (const float*)d_in[10];
    const float* w_vl  = (const float*)d_in[11];
    const float* b_vl  = (const float*)d_in[12];
    const float* w_red = (const float*)d_in[13];
    const float* bn_g  = (const float*)d_in[14];
    const float* bn_b  = (const float*)d_in[15];
    const float* bn_rm = (const float*)d_in[16];
    const float* bn_rv = (const float*)d_in[17];
    const float* w_sel = (const float*)d_in[18];
    float* out = (float*)d_out;

    k0a_init<<<32, 256>>>();
    k0b_init<<<16, 256>>>();
    k0c_init<<<1, 32>>>();
    k12<<<TOTAL_BLOCKS, 256>>>(x, w_qr, b_qr, w_ql);   // 4th launch -> ncu captures this
    k3av<<<dim3(BB, 9), 256>>>(w_vr, b_vr, b_ql, w_vl, b_vl);
    k3b<<<dim3(BB, 16), 256>>>(w_up, b_up);
    k3c<<<BB, 256>>>(ln_g, ln_b, w_red, bn_g, bn_b, bn_rm, bn_rv, w_sel);
    k45<<<dim3(BB, 32), 256>>>(x, out);
}

// round 14
// speedup vs baseline: 1.2734x; 1.2309x over previous
#include <cuda_runtime.h>
#include <cuda_bf16.h>

#define BB 16
#define CC 512
#define MM 256
#define HWN 4096
#define ATTN 32

// ---------------- scratch ----------------
__device__ float g_Y[BB*CC];
__device__ float g_S[BB];
__device__ float g_Gmax[BB*MM];
__device__ float g_ctx[BB*MM];
__device__ float g_up[BB*CC];
__device__ float g_v[BB*CC];
__device__ float g_c0[BB];
__device__ float g_P[BB*CC];
__device__ float g_Q[BB*CC];
__device__ float g_Esum[BB];
__device__ int   g_cnt[BB];

__device__ __forceinline__ void atomicMaxF(float* addr, float v) {
    int old = __float_as_int(*addr);
    while (__int_as_float(old) < v) {
        int prev = atomicCAS((int*)addr, old, __float_as_int(v));
        if (prev == old) break;
        old = prev;
    }
}

__device__ __forceinline__ float blockSum256(float v, float* red) {
    int t = threadIdx.x, lane = t & 31, warp = t >> 5;
    __syncthreads();
#pragma unroll
    for (int o = 16; o; o >>= 1) v += __shfl_xor_sync(~0u, v, o);
    if (lane == 0) red[warp] = v;
    __syncthreads();
    if (warp == 0) {
        float s = (lane < 8) ? red[lane] : 0.f;
#pragma unroll
        for (int o = 4; o; o >>= 1) s += __shfl_xor_sync(~0u, s, o);
        if (lane == 0) red[0] = s;
    }
    __syncthreads();
    return red[0];
}
__device__ __forceinline__ float blockMax256(float v, float* red) {
    int t = threadIdx.x, lane = t & 31, warp = t >> 5;
    __syncthreads();
#pragma unroll
    for (int o = 16; o; o >>= 1) v = fmaxf(v, __shfl_xor_sync(~0u, v, o));
    if (lane == 0) red[warp] = v;
    __syncthreads();
    if (warp == 0) {
        float s = (lane < 8) ? red[lane] : __int_as_float(0xff800000u);
#pragma unroll
        for (int o = 4; o; o >>= 1) s = fmaxf(s, __shfl_xor_sync(~0u, s, o));
        if (lane == 0) red[0] = s;
    }
    __syncthreads();
    return red[0];
}

// ---------------- K0 split into 3 (k12 stays the 4th launch -> profiled) ----------------
__global__ void k0a_init() {
    int i = blockIdx.x * 256 + threadIdx.x;
    if (i < BB*CC) g_Y[i] = 0.f;
}
__global__ void k0b_init() {
    int i = blockIdx.x * 256 + threadIdx.x;
    if (i < BB*MM) g_Gmax[i] = __int_as_float(0xff800000u);
}
__global__ void k0c_init() {
    int i = threadIdx.x;
    if (i < BB) { g_S[i] = 0.f; g_Esum[i] = 0.f; g_cnt[i] = 0; }
}

// ---------------- K12: interleaved k1 (mask/Y) + k2 (tensor gmax), wide-access edition ----
// bid%3==0 -> k1 role (512: b x 32 chunks of 128 px).
// else k2 role (1024: b, mt, nt): 128x128 tile, K=512.
//   A smem: As[128][40] halfwords (k-minor, pitch 80B) — ldmatrix x4.
//   B smem: Bsk[32][136] halfwords (k-major, n rows contiguous) — LDG.128 + STS.64
//           in, ldmatrix x2 TRANS out (68-word pitch: 8 rows cover 32 banks exactly).
#define TOTAL_BLOCKS (BB*96)
__global__ __launch_bounds__(256, 2) void k12(const float* __restrict__ x,
                                              const float* __restrict__ w_qr,
                                              const float* __restrict__ b_qr,
                                              const float* __restrict__ w_ql) {
    __shared__ __align__(16) char smem_raw[19456];   // A 10240 + B 8704
    int bid = blockIdx.x, t = threadIdx.x;

    if (bid % 3 == 0) {
        // ===== k1 role: 128 pixels; float4 pixel-quads, 8 channel-blocks =====
        int k1id = bid / 3;
        int b = k1id >> 5, chunk = k1id & 31;
        float*  sw     = (float*)smem_raw;            // [512]
        float4* spart4 = (float4*)(sw + CC);          // [256]
        float*  se     = (float*)(spart4 + 256);      // [128]
        for (int i = t; i < CC; i += 256) sw[i] = w_qr[i];
        __syncthreads();

        int h0 = chunk * 128;
        int q = t & 31, cb = t >> 5;                  // quad of pixels, 64-ch block
        const float* xb = x + (size_t)b * CC * HWN;
        const float* xq = xb + (size_t)(cb * 64) * HWN + h0 + q * 4;
        float4 acc = {0.f, 0.f, 0.f, 0.f};
#pragma unroll 8
        for (int c = 0; c < 64; c++) {
            float w = sw[cb * 64 + c];
            float4 xv = *(const float4*)(xq + (size_t)c * HWN);
            acc.x += w * xv.x; acc.y += w * xv.y;
            acc.z += w * xv.z; acc.w += w * xv.w;
        }
        spart4[t] = acc;                              // flat float idx = cb*128 + pixel
        __syncthreads();
        if (t < 128) {
            const float* sp = (const float*)spart4;
            float l = 0.f;
#pragma unroll
            for (int c2 = 0; c2 < 8; c2++) l += sp[c2 * 128 + t];
            float e = expf(b_qr[0] + l);
            se[t] = e;
            float s = e;
#pragma unroll
            for (int o = 16; o; o >>= 1) s += __shfl_xor_sync(~0u, s, o);
            if ((t & 31) == 0) atomicAdd(&g_S[b], s);
        }
        __syncthreads();

        // Y[c] += sum over 128 pixels; 2 rows per thread (second pass L2-hot)
        const float4* se4 = (const float4*)se;
#pragma unroll
        for (int i = 0; i < 2; i++) {
            int cc = t + i * 256;
            const float4* xr = (const float4*)(xb + (size_t)cc * HWN + h0);
            float a0 = 0.f, a1 = 0.f;
#pragma unroll 8
            for (int j = 0; j < 32; j += 2) {
                float4 xv = xr[j];     float4 ev = se4[j];
                a0 += ev.x*xv.x + ev.y*xv.y + ev.z*xv.z + ev.w*xv.w;
                float4 xw = xr[j + 1]; float4 ew = se4[j + 1];
                a1 += ew.x*xw.x + ew.y*xw.y + ew.z*xw.z + ew.w*xw.w;
            }
            atomicAdd(&g_Y[b*CC + cc], a0 + a1);
        }
    } else {
        // ===== k2 role =====
        __nv_bfloat16 (*As)[40]  = (__nv_bfloat16(*)[40])smem_raw;
        __nv_bfloat16 (*Bsk)[136] = (__nv_bfloat16(*)[136])(smem_raw + 128 * 40 * 2);
        int k2id = bid - bid / 3 - 1;
        int b = k2id >> 6, r6 = k2id & 63;
        int mt = r6 >> 5, nt = r6 & 31;
        int warp = t >> 5, lane = t & 31;
        int wm = warp >> 2, wn = warp & 3;            // 2 x 4 warps; warp tile 64x32
        const float* xb = x + (size_t)b * CC * HWN + nt * 128;
        const float* wq = w_ql + (size_t)mt * 128 * CC;

        float acc[4][4][4];
#pragma unroll
        for (int i = 0; i < 4; i++)
#pragma unroll
            for (int j = 0; j < 4; j++)
#pragma unroll
                for (int k = 0; k < 4; k++) acc[i][j][k] = 0.f;

        // prologue: stage B chunk 0 (float4 over pixels)
        float4 bstage[4];
#pragma unroll
        for (int p = 0; p < 4; p++) {
            int j = t + p * 256;
            int k = j >> 5, q = j & 31;
            bstage[p] = *(const float4*)(xb + (size_t)k * HWN + q * 4);
        }

        int a_row = (lane & 15);
        int a_c8  = (lane >> 4) << 3;
        int b_k   = (lane & 15);

        for (int k0 = 0; k0 < CC; k0 += 32) {
            __syncthreads();
#pragma unroll
            for (int p = 0; p < 4; p++) {             // B: staged -> k-major smem, STS.64
                int j = t + p * 256;
                int k = j >> 5, q = j & 31;
                __nv_bfloat162 lo = __floats2bfloat162_rn(bstage[p].x, bstage[p].y);
                __nv_bfloat162 hi = __floats2bfloat162_rn(bstage[p].z, bstage[p].w);
                uint2 val;
                val.x = *(unsigned*)&lo;
                val.y = *(unsigned*)&hi;
                *(uint2*)&Bsk[k][q * 4] = val;
            }
#pragma unroll
            for (int p = 0; p < 8; p++) {             // A: LDG.64 direct, STS.32
                int j = t + p * 256;
                int m = j >> 4, kp = j & 15;
                float2 w = *(const float2*)(wq + (size_t)m * CC + k0 + kp * 2);
                __nv_bfloat162 h2 = __floats2bfloat162_rn(w.x, w.y);
                *(unsigned*)&As[m][kp * 2] = *(unsigned*)&h2;
            }
            __syncthreads();
            if (k0 + 32 < CC) {                       // prefetch next B chunk
#pragma unroll
                for (int p = 0; p < 4; p++) {
                    int j = t + p * 256;
                    int k = j >> 5, q = j & 31;
                    bstage[p] = *(const float4*)(xb + (size_t)(k0 + 32 + k) * HWN + q * 4);
                }
            }
#pragma unroll
            for (int kb = 0; kb < 32; kb += 16) {
                unsigned af[4][4], bf[4][2];
#pragma unroll
                for (int mf = 0; mf < 4; mf++) {
                    unsigned addr = (unsigned)__cvta_generic_to_shared(
                        &As[wm * 64 + mf * 16 + a_row][kb + a_c8]);
                    asm volatile(
                        "ldmatrix.sync.aligned.m8n8.x4.shared.b16 {%0,%1,%2,%3}, [%4];"
                        : "=r"(af[mf][0]), "=r"(af[mf][1]), "=r"(af[mf][2]), "=r"(af[mf][3])
                        : "r"(addr));
                }
#pragma unroll
                for (int nf = 0; nf < 4; nf++) {
                    unsigned addr = (unsigned)__cvta_generic_to_shared(
                        &Bsk[kb + b_k][wn * 32 + nf * 8]);
                    asm volatile(
                        "ldmatrix.sync.aligned.m8n8.x2.trans.shared.b16 {%0,%1}, [%2];"
                        : "=r"(bf[nf][0]), "=r"(bf[nf][1])
                        : "r"(addr));
                }
#pragma unroll
                for (int mf = 0; mf < 4; mf++)
#pragma unroll
                    for (int nf = 0; nf < 4; nf++)
                        asm volatile(
                            "mma.sync.aligned.m16n8k16.row.col.f32.bf16.bf16.f32 "
                            "{%0,%1,%2,%3}, {%4,%5,%6,%7}, {%8,%9}, {%0,%1,%2,%3};\n"
                            : "+f"(acc[mf][nf][0]), "+f"(acc[mf][nf][1]),
                              "+f"(acc[mf][nf][2]), "+f"(acc[mf][nf][3])
                            : "r"(af[mf][0]), "r"(af[mf][1]), "r"(af[mf][2]), "r"(af[mf][3]),
                              "r"(bf[nf][0]), "r"(bf[nf][1]));
            }
        }
#pragma unroll
        for (int mf = 0; mf < 4; mf++) {
            float m0 = __int_as_float(0xff800000u), m1 = m0;
#pragma unroll
            for (int nf = 0; nf < 4; nf++) {
                m0 = fmaxf(m0, fmaxf(acc[mf][nf][0], acc[mf][nf][1]));
                m1 = fmaxf(m1, fmaxf(acc[mf][nf][2], acc[mf][nf][3]));
            }
            m0 = fmaxf(m0, __shfl_xor_sync(~0u, m0, 1));
            m0 = fmaxf(m0, __shfl_xor_sync(~0u, m0, 2));
            m1 = fmaxf(m1, __shfl_xor_sync(~0u, m1, 1));
            m1 = fmaxf(m1, __shfl_xor_sync(~0u, m1, 2));
            if ((lane & 3) == 0) {
                int r = mt * 128 + wm * 64 + mf * 16 + (lane >> 2);
                atomicMaxF(&g_Gmax[b * MM + r], m0);
                atomicMaxF(&g_Gmax[b * MM + r + 8], m1);
            }
        }
    }
}

// ---------------- K3av: blk 0..7 -> context rows; blk 8 -> softmax/v/c0.  grid (B,9) ----------------
__global__ void k3av(const float* __restrict__ w_vr, const float* __restrict__ b_vr,
                     const float* __restrict__ b_ql,
                     const float* __restrict__ w_vl, const float* __restrict__ b_vl) {
    int b = blockIdx.x, blk = blockIdx.y, t = threadIdx.x;
    int warp = t >> 5, lane = t & 31;
    if (blk < 8) {
        __shared__ float sy[CC];
        float Sinv = 1.f / g_S[b];
        for (int i = t; i < CC; i += 256) sy[i] = g_Y[b*CC + i] * Sinv;
        __syncthreads();
#pragma unroll
        for (int i = 0; i < 4; i++) {
            int r = blk * 32 + warp * 4 + i;
            const float* wr = w_vr + (size_t)r * CC;
            float a = 0.f;
#pragma unroll
            for (int c = lane; c < CC; c += 32) a += wr[c] * sy[c];
#pragma unroll
            for (int o = 16; o; o >>= 1) a += __shfl_xor_sync(~0u, a, o);
            if (lane == 0) g_ctx[b*MM + r] = a + b_vr[r];
        }
    } else {
        __shared__ float savg[MM];
        __shared__ float red[8];
        float gv = g_Gmax[b*MM + t] + b_ql[t];
        float gm = blockMax256(gv, red);
        float ge = expf(gv - gm);
        float gs = blockSum256(ge, red);
        savg[t] = ge / gs;
        float c0 = blockSum256((ge / gs) * b_vl[t], red);
        if (t == 0) g_c0[b] = c0;
        __syncthreads();
        float a0 = 0.f, a1 = 0.f;
#pragma unroll 8
        for (int m = 0; m < MM; m++) {
            float av = savg[m];
            const float* wr = w_vl + (size_t)m * CC;
            a0 += av * wr[t];
            a1 += av * wr[t + 256];
        }
        g_v[b*CC + t]       = a0;
        g_v[b*CC + t + 256] = a1;
    }
}

// ---------------- K3b: up = W_up @ ctx + b_up.  grid (B, 16) ----------------
__global__ void k3b(const float* __restrict__ w_up, const float* __restrict__ b_up) {
    __shared__ float sc[MM];
    int b = blockIdx.x, blk = blockIdx.y, t = threadIdx.x;
    int warp = t >> 5, lane = t & 31;
    if (t < MM) sc[t] = g_ctx[b*MM + t];
    __syncthreads();
#pragma unroll
    for (int i = 0; i < 4; i++) {
        int r = blk * 32 + warp * 4 + i;
        const float* wr = w_up + (size_t)r * MM;
        float a = 0.f;
#pragma unroll
        for (int m = lane; m < MM; m += 32) a += wr[m] * sc[m];
#pragma unroll
        for (int o = 16; o; o >>= 1) a += __shfl_xor_sync(~0u, a, o);
        if (lane == 0) g_up[b*CC + r] = a + b_up[r];
    }
}

// ---------------- K3c: LN + sigmoid + SK-attn -> P,Q.  grid B ----------------
__global__ void k3c(const float* __restrict__ ln_g, const float* __restrict__ ln_b,
                    const float* __restrict__ w_red, const float* __restrict__ bn_g,
                    const float* __restrict__ bn_b, const float* __restrict__ bn_rm,
                    const float* __restrict__ bn_rv, const float* __restrict__ w_sel) {
    __shared__ float sy[CC];
    __shared__ float sca[CC];
    __shared__ float ssk[ATTN];
    __shared__ float red[8];
    int b = blockIdx.x, t = threadIdx.x;
    int warp = t >> 5, lane = t & 31;

    float u0 = g_up[b*CC + t], u1 = g_up[b*CC + t + 256];
    float mean = blockSum256(u0 + u1, red) * (1.f / CC);
    float var  = blockSum256(u0*u0 + u1*u1, red) * (1.f / CC) - mean * mean;
    float rstd = rsqrtf(var + 1e-5f);
    sca[t]       = 1.f / (1.f + expf(-((u0 - mean) * rstd * ln_g[t] + ln_b[t])));
    sca[t + 256] = 1.f / (1.f + expf(-((u1 - mean) * rstd * ln_g[t + 256] + ln_b[t + 256])));

    const float invHW = 1.f / (float)HWN;
    sy[t]       = sca[t]       * (1.f + invHW) + invHW;
    sy[t + 256] = sca[t + 256] * (1.f + invHW) + invHW;
    __syncthreads();

#pragma unroll
    for (int i = 0; i < 4; i++) {
        int r = warp * 4 + i;
        const float* wr = w_red + (size_t)r * CC;
        float a = 0.f;
#pragma unroll
        for (int c = lane; c < CC; c += 32) a += wr[c] * sy[c];
#pragma unroll
        for (int o = 16; o; o >>= 1) a += __shfl_xor_sync(~0u, a, o);
        if (lane == 0) {
            a = (a - bn_rm[r]) * rsqrtf(bn_rv[r] + 1e-5f) * bn_g[r] + bn_b[r];
            ssk[r] = fmaxf(a, 0.f);
        }
    }
    __syncthreads();

#pragma unroll
    for (int i = 0; i < 2; i++) {
        int c = t + i * 256;
        float s0 = 0.f, s1 = 0.f;
        const float* w0 = w_sel + (size_t)c * ATTN;
        const float* w1 = w_sel + (size_t)(CC + c) * ATTN;
#pragma unroll
        for (int a = 0; a < ATTN; a++) { s0 += w0[a] * ssk[a]; s1 += w1[a] * ssk[a]; }
        float mx = fmaxf(s0, s1);
        float e0 = expf(s0 - mx), e1 = expf(s1 - mx);
        float inv = 1.f / (e0 + e1);
        float a0 = e0 * inv, a1 = e1 * inv;
        float ca = sca[c];
        g_P[b*CC + c] = a0 * ca + a1;
        g_Q[b*CC + c] = a1 * ca;
    }
}

// ---------------- K45: fused ctx+exp+Esum (per-batch spin barrier) + final output ----
__global__ __launch_bounds__(256) void k45(const float* __restrict__ x,
                                           float* __restrict__ out) {
    __shared__ float sv[CC];
    __shared__ float sP[CC];
    __shared__ float sQ[CC];
    __shared__ float spart[256];
    __shared__ float se[128];
    __shared__ float red[4];
    __shared__ float sEinv;
    int b = blockIdx.x, chunk = blockIdx.y, t = threadIdx.x;
    for (int i = t; i < CC; i += 256) {
        sv[i] = g_v[b*CC + i];
        sP[i] = g_P[b*CC + i];
        sQ[i] = g_Q[b*CC + i];
    }
    __syncthreads();

    int p = t & 127, half = t >> 7;
    int c0 = half * 256;
    int h0 = chunk * 128;
    const float* xb = x + (size_t)b * CC * HWN;
    const float* xp = xb + (size_t)c0 * HWN + h0 + p;
    float a0 = 0.f, a1 = 0.f, a2 = 0.f, a3 = 0.f;
#pragma unroll 8
    for (int c = 0; c < 256; c += 4) {
        a0 += sv[c0 + c]     * xp[(size_t)c * HWN];
        a1 += sv[c0 + c + 1] * xp[(size_t)(c + 1) * HWN];
        a2 += sv[c0 + c + 2] * xp[(size_t)(c + 2) * HWN];
        a3 += sv[c0 + c + 3] * xp[(size_t)(c + 3) * HWN];
    }
    spart[t] = (a0 + a1) + (a2 + a3);
    __syncthreads();
    if (t < 128) {
        float e = expf(g_c0[b] + spart[t] + spart[t + 128]);
        se[t] = e;
        float s = e;
#pragma unroll
        for (int o = 16; o; o >>= 1) s += __shfl_xor_sync(~0u, s, o);
        if ((t & 31) == 0) red[t >> 5] = s;
    }
    __syncthreads();
    if (t == 0) {
        atomicAdd(&g_Esum[b], (red[0] + red[1]) + (red[2] + red[3]));
        __threadfence();
        atomicAdd(&g_cnt[b], 1);
        volatile int* vc = (volatile int*)&g_cnt[b];
        while (*vc < 32) { }
        __threadfence();
        sEinv = 1.f / *((volatile float*)&g_Esum[b]);
    }
    __syncthreads();
    float inv = sEinv;

    const float4* se4 = (const float4*)se;
    const float4* x4 = (const float4*)(xb + h0);
    float4* o4 = (float4*)(out + (size_t)b * CC * HWN + h0);
    for (int i = t; i < CC * 32; i += 256) {
        int row = i >> 5, f4 = i & 31;
        float4 xv = x4[(size_t)row * (HWN/4) + f4];
        float4 ev = se4[f4];
        float P = sP[row], base = 1.f + sQ[row];
        float4 o;
        o.x = xv.x * (base + P * ev.x * inv);
        o.y = xv.y * (base + P * ev.y * inv);
        o.z = xv.z * (base + P * ev.z * inv);
        o.w = xv.w * (base + P * ev.w * inv);
        o4[(size_t)row * (HWN/4) + f4] = o;
    }
}

// ---------------- launch ----------------
extern "C" void kernel_launch(void* const* d_in, const int* in_sizes, int n_in,
                              void* d_out, int out_size) {
    const float* x     = (const float*)d_in[0];
    const float* w_qr  = (const float*)d_in[1];
    const float* b_qr  = (const float*)d_in[2];
    const float* w_vr  = (const float*)d_in[3];
    const float* b_vr  = (const float*)d_in[4];
    const float* w_up  = (const float*)d_in[5];
    const float* b_up  = (const float*)d_in[6];
    const float* ln_g  = (const float*)d_in[7];
    const float* ln_b  = (const float*)d_in[8];
    const float* w_ql  = (const float*)d_in[9];
    const float* b_ql  = (const float*)d_in[10];
    const float* w_vl  = (const float*)d_in[11];
    const float* b_vl  = (const float*)d_in[12];
    const float* w_red = (const float*)d_in[13];
    const float* bn_g  = (const float*)d_in[14];
    const float* bn_b  = (const float*)d_in[15];
    const float* bn_rm = (const float*)d_in[16];
    const float* bn_rv = (const float*)d_in[17];
    const float* w_sel = (const float*)d_in[18];
    float* out = (float*)d_out;

    k0a_init<<<32, 256>>>();
    k0b_init<<<16, 256>>>();
    k0c_init<<<1, 32>>>();
    k12<<<TOTAL_BLOCKS, 256>>>(x, w_qr, b_qr, w_ql);   // 4th launch -> ncu captures this
    k3av<<<dim3(BB, 9), 256>>>(w_vr, b_vr, b_ql, w_vl, b_vl);
    k3b<<<dim3(BB, 16), 256>>>(w_up, b_up);
    k3c<<<BB, 256>>>(ln_g, ln_b, w_red, bn_g, bn_b, bn_rm, bn_rv, w_sel);
    k45<<<dim3(BB, 32), 256>>>(x, out);
}